// round 6
// baseline (speedup 1.0000x reference)
#include <cuda_runtime.h>
#include <cuda_bf16.h>
#include <math.h>

#define NSEQ 256
#define CZ   128
#define NH   4
#define HD   32
#define RTOT (NSEQ * NSEQ)

typedef unsigned int u32;
typedef unsigned long long u64;

// ---------------- global scratch ----------------
// Q/K/V stored split bf16 (hi+lo), Q pre-scaled by 1/sqrt(32)
__device__ __nv_bfloat16 g_Qhi[(size_t)RTOT * CZ];
__device__ __nv_bfloat16 g_Qlo[(size_t)RTOT * CZ];
__device__ __nv_bfloat16 g_Khi[(size_t)RTOT * CZ];
__device__ __nv_bfloat16 g_Klo[(size_t)RTOT * CZ];
__device__ __nv_bfloat16 g_Vhi[(size_t)RTOT * CZ];
__device__ __nv_bfloat16 g_Vlo[(size_t)RTOT * CZ];
__device__ float g_G[(size_t)RTOT * CZ];
__device__ float g_BiasT[(size_t)NH * RTOT];
__device__ float g_AV[(size_t)RTOT * CZ];
__device__ __nv_bfloat16 g_WtHi[5][CZ * CZ];
__device__ __nv_bfloat16 g_WtLo[5][CZ * CZ];

// ---------------- helpers ----------------
__device__ __forceinline__ u32 smem_u32(const void* p) {
    u32 a;
    asm("{ .reg .u64 t; cvta.to.shared.u64 t, %1; cvt.u32.u64 %0, t; }" : "=r"(a) : "l"(p));
    return a;
}
__device__ __forceinline__ void ldsm_x4(u32* r, u32 addr) {
    asm volatile("ldmatrix.sync.aligned.m8n8.x4.shared.b16 {%0,%1,%2,%3}, [%4];"
        : "=r"(r[0]), "=r"(r[1]), "=r"(r[2]), "=r"(r[3]) : "r"(addr));
}
__device__ __forceinline__ void ldsm_x4_t(u32* r, u32 addr) {
    asm volatile("ldmatrix.sync.aligned.m8n8.x4.trans.shared.b16 {%0,%1,%2,%3}, [%4];"
        : "=r"(r[0]), "=r"(r[1]), "=r"(r[2]), "=r"(r[3]) : "r"(addr));
}
__device__ __forceinline__ void mma_bf16(float* d, const u32* a, const u32* b) {
    asm volatile("mma.sync.aligned.m16n8k16.row.col.f32.bf16.bf16.f32 "
        "{%0,%1,%2,%3}, {%4,%5,%6,%7}, {%8,%9}, {%0,%1,%2,%3};"
        : "+f"(d[0]), "+f"(d[1]), "+f"(d[2]), "+f"(d[3])
        : "r"(a[0]), "r"(a[1]), "r"(a[2]), "r"(a[3]), "r"(b[0]), "r"(b[1]));
}
__device__ __forceinline__ u32 pack_bf2(float x, float y) {
    __nv_bfloat162 t;
    t.x = __float2bfloat16(x);
    t.y = __float2bfloat16(y);
    return *(u32*)&t;
}
__device__ __forceinline__ void split_pack(float x, float y, u32& h, u32& l) {
    __nv_bfloat16 hx = __float2bfloat16(x);
    __nv_bfloat16 hy = __float2bfloat16(y);
    __nv_bfloat162 hh; hh.x = hx; hh.y = hy;
    h = *(u32*)&hh;
    l = pack_bf2(x - __bfloat162float(hx), y - __bfloat162float(hy));
}
__device__ __forceinline__ void cp16(u32 dst, const void* src) {
    u64 g;
    asm("cvta.to.global.u64 %0, %1;" : "=l"(g) : "l"(src));
    asm volatile("cp.async.ca.shared.global [%0], [%1], 16;" :: "r"(dst), "l"(g));
}
#define CP_COMMIT() asm volatile("cp.async.commit_group;")
#define CP_WAIT(n)  asm volatile("cp.async.wait_group %0;" :: "n"(n))

#define TSTRIDE 136
#define THALF   34816     // 128 rows * 136 * 2B (one half of a 128-row split tile)

// lnproj smem
#define LNP_SA   0
#define LNP_SB0  69632
#define LNP_SB1  139264
#define LNP_XS   69632
#define LNP_WB   (69632 + 66048)
#define LNP_SMEM 208896
// outproj smem (64-row tiles)
#define OP_AHALF 17408    // 64 * 136 * 2
#define OP_SA    0
#define OP_SB    34816
#define OP_SMEM  104448

// ---------------------------------------------------------------------------
// Kernel 0: transpose + hi/lo-split weights
// ---------------------------------------------------------------------------
__global__ void wtransform(const float* __restrict__ Wq, const float* __restrict__ Wk,
                           const float* __restrict__ Wv, const float* __restrict__ Wg,
                           const float* __restrict__ Wo)
{
    const float* W = (blockIdx.x == 0) ? Wq : (blockIdx.x == 1) ? Wk :
                     (blockIdx.x == 2) ? Wv : (blockIdx.x == 3) ? Wg : Wo;
    __nv_bfloat16* H = g_WtHi[blockIdx.x];
    __nv_bfloat16* L = g_WtLo[blockIdx.x];
    for (int e = threadIdx.x; e < CZ * CZ; e += blockDim.x) {
        int n = e >> 7, c = e & 127;
        float a = W[c * CZ + n];
        __nv_bfloat16 hi = __float2bfloat16(a);
        H[e] = hi;
        L[e] = __float2bfloat16(a - __bfloat162float(hi));
    }
}

// ---------------------------------------------------------------------------
// GEMM warp mainloop: 16 rows x 64 cols; A reloaded per ks (no spill)
// ---------------------------------------------------------------------------
__device__ __forceinline__ void gemm_warp(float acc[8][4], u32 aBase, u32 aHalf, u32 bBase)
{
#pragma unroll
    for (int ks = 0; ks < 8; ks++) {
        u32 ah[4], al[4];
        ldsm_x4(ah, aBase + ks * 32);
        ldsm_x4(al, aBase + aHalf + ks * 32);
#pragma unroll
        for (int p = 0; p < 4; p++) {
            u32 ba = bBase + (u32)(p * 16 * TSTRIDE) * 2 + ks * 32;
            u32 bh[4], bl[4];
            ldsm_x4(bh, ba);
            ldsm_x4(bl, ba + THALF);
            mma_bf16(acc[2 * p],     ah, bh);
            mma_bf16(acc[2 * p + 1], ah, bh + 2);
            mma_bf16(acc[2 * p],     al, bh);
            mma_bf16(acc[2 * p + 1], al, bh + 2);
            mma_bf16(acc[2 * p],     ah, bl);
            mma_bf16(acc[2 * p + 1], ah, bl + 2);
        }
    }
}

__device__ __forceinline__ void cp_weights(u32 sb, u32 bufOff, int m, int tid, int nthr)
{
    for (int e = tid; e < 4096; e += nthr) {
        int half = e >> 11, rem = e & 2047, n = rem >> 4, ch = rem & 15;
        const __nv_bfloat16* src = (half ? g_WtLo[m] : g_WtHi[m]) + n * 128 + ch * 8;
        u32 dst = sb + bufOff + (u32)half * THALF + (u32)(n * TSTRIDE + ch * 8) * 2;
        cp16(dst, src);
    }
    CP_COMMIT();
}

// ---------------------------------------------------------------------------
// Kernel 1: LN + Q/K/V/G projections; Q/K/V written split-bf16 (Q pre-scaled)
// ---------------------------------------------------------------------------
__global__ __launch_bounds__(512) void lnproj_mma(const float* __restrict__ x,
                                                  const float* __restrict__ gamma,
                                                  const float* __restrict__ beta,
                                                  const float* __restrict__ Wb,
                                                  const float* __restrict__ bg)
{
    extern __shared__ char sm[];
    const u32 sb = smem_u32(sm);
    const int tid = threadIdx.x, wid = tid >> 5, lane = tid & 31;
    const int wr = wid & 7, wc = wid >> 3;
    const size_t r0 = (size_t)blockIdx.x * 128;
    float* xs  = (float*)(sm + LNP_XS);
    float* sWb = (float*)(sm + LNP_WB);

    const float4* xg = (const float4*)(x + r0 * CZ);
    for (int i = tid; i < 4096; i += 512) {
        float4 v = xg[i];
        int row = i >> 5, c = (i & 31) << 2;
        float* d = xs + row * 129 + c;
        d[0] = v.x; d[1] = v.y; d[2] = v.z; d[3] = v.w;
    }
    sWb[tid] = Wb[tid];
    __syncthreads();

    if (tid < 128) {
        float* row = xs + tid * 129;
        float s = 0.f, s2 = 0.f;
#pragma unroll 8
        for (int c = 0; c < 128; c++) { float v = row[c]; s += v; s2 += v * v; }
        float mu  = s * (1.f / 128.f);
        float var = s2 * (1.f / 128.f) - mu * mu;
        float inv = rsqrtf(var + 1e-5f);
#pragma unroll 8
        for (int c = 0; c < 128; c++)
            row[c] = (row[c] - mu) * inv * gamma[c] + beta[c];
    }
    __syncthreads();

    {
        int row = tid >> 2, h = tid & 3;
        const float* xr = xs + row * 129;
        float s = 0.f;
#pragma unroll 8
        for (int c = 0; c < 128; c++) s += xr[c] * sWb[c * 4 + h];
        g_BiasT[(size_t)h * RTOT + r0 + row] = s;
    }
    for (int p = tid; p < 8192; p += 512) {
        int row = p >> 6, c = (p & 63) << 1;
        u32 hh, ll;
        split_pack(xs[row * 129 + c], xs[row * 129 + c + 1], hh, ll);
        u32 off = (u32)(row * TSTRIDE + c) * 2;
        *(u32*)(sm + LNP_SA + off)         = hh;
        *(u32*)(sm + LNP_SA + THALF + off) = ll;
    }
    cp_weights(sb, LNP_SB1, 0, tid, 512);
    __syncthreads();

    const int i_ = lane >> 3, r_ = lane & 7;
    const u32 aBase = sb + LNP_SA +
        (u32)((wr * 16 + ((i_ & 1) << 3) + r_) * TSTRIDE + ((i_ >> 1) << 3)) * 2;
    const u32 bOffW = (u32)((wc * 64 + ((i_ >> 1) << 3) + r_) * TSTRIDE + ((i_ & 1) << 3)) * 2;
    const int g = lane >> 2, tig = lane & 3;
    const size_t rowA = r0 + wr * 16 + g;
    const size_t rowB = rowA + 8;

#pragma unroll
    for (int m = 0; m < 4; m++) {
        if (m < 3) cp_weights(sb, (m & 1) ? LNP_SB1 : LNP_SB0, m + 1, tid, 512);
        if (m < 3) { CP_WAIT(1); } else { CP_WAIT(0); }
        __syncthreads();

        const u32 bufOff = (m & 1) ? LNP_SB0 : LNP_SB1;
        float acc[8][4];
#pragma unroll
        for (int t = 0; t < 8; t++)
#pragma unroll
            for (int v = 0; v < 4; v++) acc[t][v] = 0.f;

        gemm_warp(acc, aBase, THALF, sb + bufOff + bOffW);

        if (m < 3) {
            __nv_bfloat16* Ohi = (m == 0) ? g_Qhi : (m == 1) ? g_Khi : g_Vhi;
            __nv_bfloat16* Olo = (m == 0) ? g_Qlo : (m == 1) ? g_Klo : g_Vlo;
            const float qs = (m == 0) ? 0.17677669529663689f : 1.f;
#pragma unroll
            for (int nt = 0; nt < 8; nt++) {
                int col = wc * 64 + nt * 8 + tig * 2;
                u32 hA, lA, hB, lB;
                split_pack(acc[nt][0] * qs, acc[nt][1] * qs, hA, lA);
                split_pack(acc[nt][2] * qs, acc[nt][3] * qs, hB, lB);
                *(u32*)(Ohi + rowA * CZ + col) = hA;
                *(u32*)(Olo + rowA * CZ + col) = lA;
                *(u32*)(Ohi + rowB * CZ + col) = hB;
                *(u32*)(Olo + rowB * CZ + col) = lB;
            }
        } else {
#pragma unroll
            for (int nt = 0; nt < 8; nt++) {
                int col = wc * 64 + nt * 8 + tig * 2;
                float2 bgv = __ldg((const float2*)(bg + col));
                float2 oA, oB;
                oA.x = 1.f / (1.f + __expf(-(acc[nt][0] + bgv.x)));
                oA.y = 1.f / (1.f + __expf(-(acc[nt][1] + bgv.y)));
                oB.x = 1.f / (1.f + __expf(-(acc[nt][2] + bgv.x)));
                oB.y = 1.f / (1.f + __expf(-(acc[nt][3] + bgv.y)));
                *(float2*)(g_G + rowA * CZ + col) = oA;
                *(float2*)(g_G + rowB * CZ + col) = oB;
            }
        }
        __syncthreads();
    }
}

// ---------------------------------------------------------------------------
// Kernel 2: attention. K/V staged via cp.async (pre-split); V via ldmatrix.trans.
// Grid (256, 8): blockIdx.x = i, blockIdx.y = h*2 + jhalf. 8 warps x 16 j-rows.
// ---------------------------------------------------------------------------
#define KSTR 40
#define AT_BUF 20480      // 256 * 40 * 2
#define AT_SMEM (4 * AT_BUF)

__global__ __launch_bounds__(256, 2) void attn_mma()
{
    extern __shared__ char sm[];
    const u32 sb = smem_u32(sm);
    const int tid = threadIdx.x, wid = tid >> 5, lane = tid & 31;
    const int bi = blockIdx.x;
    const int h  = blockIdx.y >> 1;
    const int jh = blockIdx.y & 1;
    const size_t base = ((size_t)bi * NSEQ) * CZ + (size_t)h * HD;

    // stage Khi | Klo | Vhi | Vlo rows [256][32] via cp.async
    for (int e = tid; e < 4096; e += 256) {
        int buf = e >> 10, rem = e & 1023, k = rem >> 2, ch = rem & 3;
        const __nv_bfloat16* src =
            ((buf == 0) ? g_Khi : (buf == 1) ? g_Klo : (buf == 2) ? g_Vhi : g_Vlo)
            + base + (size_t)k * CZ + ch * 8;
        u32 dst = sb + (u32)buf * AT_BUF + (u32)(k * KSTR + ch * 8) * 2;
        cp16(dst, src);
    }
    CP_COMMIT();

    const int jr = jh * 128 + wid * 16;
    const int r  = lane >> 2, c2 = (lane & 3) << 1;

    // Q fragments: direct u32 loads (pre-scaled, pre-split)
    u32 qhi[2][4], qlo[2][4];
#pragma unroll
    for (int ks = 0; ks < 2; ks++)
#pragma unroll
        for (int reg = 0; reg < 4; reg++) {
            int row = jr + r + (reg & 1) * 8;
            int col = ks * 16 + c2 + ((reg >> 1) << 3);
            qhi[ks][reg] = *(const u32*)(g_Qhi + base + (size_t)row * CZ + col);
            qlo[ks][reg] = *(const u32*)(g_Qlo + base + (size_t)row * CZ + col);
        }

    CP_WAIT(0);
    __syncthreads();

    const int i_ = lane >> 3, r_ = lane & 7;
    const int brow = ((i_ >> 1) << 3) + r_;   // K ldsm row sel (non-trans)
    const int bcol = (i_ & 1) << 3;
    // V trans-ldsm addressing: lane l of sel s -> row (s&1)*8 + (l&7), col (s>>1)*8
    const int vsel = lane >> 3, vrow = lane & 7;
    const u32 vOff = (u32)(((vsel & 1) * 8 + vrow) * KSTR + ((vsel >> 1) << 3)) * 2;

    float oacc[4][4];
#pragma unroll
    for (int t = 0; t < 4; t++)
#pragma unroll
        for (int v = 0; v < 4; v++) oacc[t][v] = 0.f;
    float lsum0 = 0.f, lsum1 = 0.f;

    const float* bias0 = g_BiasT + (size_t)h * RTOT + (size_t)(jr + r) * NSEQ;
    const float* bias1 = bias0 + 8 * NSEQ;

    for (int kc = 0; kc < 4; kc++) {
        float sacc[8][4];
#pragma unroll
        for (int t = 0; t < 8; t++)
#pragma unroll
            for (int v = 0; v < 4; v++) sacc[t][v] = 0.f;

        // ---- S = Q K^T (3-term split) ----
#pragma unroll
        for (int p4 = 0; p4 < 4; p4++) {
#pragma unroll
            for (int ks = 0; ks < 2; ks++) {
                u32 addr = sb + (u32)((kc * 64 + p4 * 16 + brow) * KSTR + ks * 16 + bcol) * 2;
                u32 bh[4], bl[4];
                ldsm_x4(bh, addr);
                ldsm_x4(bl, addr + AT_BUF);
                mma_bf16(sacc[2 * p4],     qhi[ks], bh);
                mma_bf16(sacc[2 * p4 + 1], qhi[ks], bh + 2);
                mma_bf16(sacc[2 * p4],     qlo[ks], bh);
                mma_bf16(sacc[2 * p4 + 1], qlo[ks], bh + 2);
                mma_bf16(sacc[2 * p4],     qhi[ks], bl);
                mma_bf16(sacc[2 * p4 + 1], qhi[ks], bl + 2);
            }
        }

        // ---- bias + exp (no-max; scores bounded) ----
#pragma unroll
        for (int nt = 0; nt < 8; nt++) {
            int kcol = kc * 64 + nt * 8 + c2;
            float2 b0 = __ldg((const float2*)(bias0 + kcol));
            float2 b1 = __ldg((const float2*)(bias1 + kcol));
            float p00 = __expf(sacc[nt][0] + b0.x);
            float p01 = __expf(sacc[nt][1] + b0.y);
            float p10 = __expf(sacc[nt][2] + b1.x);
            float p11 = __expf(sacc[nt][3] + b1.y);
            sacc[nt][0] = p00; sacc[nt][1] = p01;
            sacc[nt][2] = p10; sacc[nt][3] = p11;
            lsum0 += p00 + p01;
            lsum1 += p10 + p11;
        }

        // ---- O += P V (3-term; V B-frags via ldmatrix.trans on [k][d] rows) ----
#pragma unroll
        for (int ks2 = 0; ks2 < 4; ks2++) {
            u32 phi[4], plo[4];
            {
                const float* s0 = sacc[2 * ks2];
                const float* s1 = sacc[2 * ks2 + 1];
                u32 h0, l0, h1, l1, h2, l2, h3, l3;
                split_pack(s0[0], s0[1], h0, l0);
                split_pack(s0[2], s0[3], h1, l1);
                split_pack(s1[0], s1[1], h2, l2);
                split_pack(s1[2], s1[3], h3, l3);
                phi[0] = h0; phi[1] = h1; phi[2] = h2; phi[3] = h3;
                plo[0] = l0; plo[1] = l1; plo[2] = l2; plo[3] = l3;
            }
            u32 a0 = sb + 2u * AT_BUF + (u32)((kc * 64 + ks2 * 16) * KSTR) * 2 + vOff;
            u32 vh[8], vl[8];
            ldsm_x4_t(vh,     a0);
            ldsm_x4_t(vh + 4, a0 + 32);        // d 16..31
            ldsm_x4_t(vl,     a0 + AT_BUF);
            ldsm_x4_t(vl + 4, a0 + AT_BUF + 32);
#pragma unroll
            for (int ntd = 0; ntd < 4; ntd++) {
                mma_bf16(oacc[ntd], phi, vh + 2 * ntd);
                mma_bf16(oacc[ntd], plo, vh + 2 * ntd);
                mma_bf16(oacc[ntd], phi, vl + 2 * ntd);
            }
        }
    }

    lsum0 += __shfl_xor_sync(0xFFFFFFFF, lsum0, 1);
    lsum0 += __shfl_xor_sync(0xFFFFFFFF, lsum0, 2);
    lsum1 += __shfl_xor_sync(0xFFFFFFFF, lsum1, 1);
    lsum1 += __shfl_xor_sync(0xFFFFFFFF, lsum1, 2);
    const float inv0 = __fdividef(1.f, lsum0);
    const float inv1 = __fdividef(1.f, lsum1);

    const size_t row0 = base + (size_t)(jr + r) * CZ;
    const size_t row1 = row0 + 8 * CZ;
#pragma unroll
    for (int ntd = 0; ntd < 4; ntd++) {
        int col = ntd * 8 + c2;
        float2 g0 = __ldg((const float2*)(g_G + row0 + col));
        float2 g1 = __ldg((const float2*)(g_G + row1 + col));
        float2 o0, o1;
        o0.x = oacc[ntd][0] * inv0 * g0.x;
        o0.y = oacc[ntd][1] * inv0 * g0.y;
        o1.x = oacc[ntd][2] * inv1 * g1.x;
        o1.y = oacc[ntd][3] * inv1 * g1.y;
        *(float2*)(g_AV + row0 + col) = o0;
        *(float2*)(g_AV + row1 + col) = o1;
    }
}

// ---------------------------------------------------------------------------
// Kernel 3: output projection, 64-row CTAs (2 CTA/SM), 256 threads
// ---------------------------------------------------------------------------
__global__ __launch_bounds__(256, 2) void outproj_mma(const float* __restrict__ bo_,
                                                      float* __restrict__ out)
{
    extern __shared__ char sm[];
    const u32 sb = smem_u32(sm);
    const int tid = threadIdx.x, wid = tid >> 5, lane = tid & 31;
    const int wr = wid & 3, wc = wid >> 2;
    const size_t r0 = (size_t)blockIdx.x * 64;

    cp_weights(sb, OP_SB, 4, tid, 256);

    for (int p = tid; p < 4096; p += 256) {
        int row = p >> 6, c = (p & 63) << 1;
        float2 v = *(const float2*)(g_AV + (r0 + row) * CZ + c);
        u32 hh, ll;
        split_pack(v.x, v.y, hh, ll);
        u32 off = (u32)(row * TSTRIDE + c) * 2;
        *(u32*)(sm + OP_SA + off)            = hh;
        *(u32*)(sm + OP_SA + OP_AHALF + off) = ll;
    }
    CP_WAIT(0);
    __syncthreads();

    const int i_ = lane >> 3, r_ = lane & 7;
    const u32 aBase = sb + OP_SA +
        (u32)((wr * 16 + ((i_ & 1) << 3) + r_) * TSTRIDE + ((i_ >> 1) << 3)) * 2;
    const u32 bBase = sb + OP_SB +
        (u32)((wc * 64 + ((i_ >> 1) << 3) + r_) * TSTRIDE + ((i_ & 1) << 3)) * 2;

    float acc[8][4];
#pragma unroll
    for (int t = 0; t < 8; t++)
#pragma unroll
        for (int v = 0; v < 4; v++) acc[t][v] = 0.f;

    gemm_warp(acc, aBase, OP_AHALF, bBase);

    const int g = lane >> 2, tig = lane & 3;
    const size_t rowA = r0 + wr * 16 + g;
    const size_t rowB = rowA + 8;
#pragma unroll
    for (int nt = 0; nt < 8; nt++) {
        int col = wc * 64 + nt * 8 + tig * 2;
        float2 bov = __ldg((const float2*)(bo_ + col));
        *(float2*)(out + rowA * CZ + col) = make_float2(acc[nt][0] + bov.x, acc[nt][1] + bov.y);
        *(float2*)(out + rowB * CZ + col) = make_float2(acc[nt][2] + bov.x, acc[nt][3] + bov.y);
    }
}

// ---------------------------------------------------------------------------
extern "C" void kernel_launch(void* const* d_in, const int* in_sizes, int n_in,
                              void* d_out, int out_size)
{
    const float* x     = (const float*)d_in[0];
    const float* gamma = (const float*)d_in[1];
    const float* beta  = (const float*)d_in[2];
    const float* Wq    = (const float*)d_in[3];
    const float* Wk    = (const float*)d_in[4];
    const float* Wv    = (const float*)d_in[5];
    const float* Wb    = (const float*)d_in[6];
    const float* Wg    = (const float*)d_in[7];
    const float* bg    = (const float*)d_in[8];
    const float* Wo    = (const float*)d_in[9];
    const float* bo    = (const float*)d_in[10];
    float* out = (float*)d_out;

    cudaFuncSetAttribute(lnproj_mma,  cudaFuncAttributeMaxDynamicSharedMemorySize, LNP_SMEM);
    cudaFuncSetAttribute(outproj_mma, cudaFuncAttributeMaxDynamicSharedMemorySize, OP_SMEM);
    cudaFuncSetAttribute(attn_mma,    cudaFuncAttributeMaxDynamicSharedMemorySize, AT_SMEM);

    wtransform<<<5, 256>>>(Wq, Wk, Wv, Wg, Wo);
    lnproj_mma<<<RTOT / 128, 512, LNP_SMEM>>>(x, gamma, beta, Wb, bg);
    dim3 g2(NSEQ, 2 * NH);
    attn_mma<<<g2, 256, AT_SMEM>>>();
    outproj_mma<<<RTOT / 64, 256, OP_SMEM>>>(bo, out);
}